// round 12
// baseline (speedup 1.0000x reference)
#include <cuda_runtime.h>
#include <cstdint>

#define BATCH 16
#define TT    1024
#define FF    128
#define RR    2048
#define HALF  1024
#define GAMMA 0.95f

#define NCTA          128
#define ROWS_PER_CTA  16
#define NTHREADS      256
#define CHUNK         512
#define NCHUNK        4

// SMEM layout (floats), padded strides to kill LDS.64 bank conflicts
#define WPAD   2050          // W row stride (16 rows)
#define HPAD   516           // h chunk row stride (16 batches), 16B-aligned rows
#define SW_FLOATS   (ROWS_PER_CTA * WPAD)          // 32800
#define SH_FLOATS   (2 * BATCH * HPAD)             // 16512
#define SMEM_MAIN   ((SW_FLOATS + SH_FLOATS) * 4)  // 197248 B

#define PPAD   130
#define SMEM_PROJ   ((128 * PPAD + BATCH * PPAD) * 4)  // 74880 B

typedef unsigned long long ull;

// ---------------- device globals (no allocations allowed) ----------------
__device__ float   g_proj[(size_t)TT * BATCH * HALF];  // [t][b][r<HALF], 64 MB
__device__ float   g_h[2][BATCH * RR];                 // ping-pong state
__device__ unsigned g_bar = 0;                         // monotonic ticket barrier

// ---------------- helpers ----------------
__device__ __forceinline__ ull ffma2(ull a, ull b, ull c) {
    ull d;
    asm("fma.rn.f32x2 %0, %1, %2, %3;" : "=l"(d) : "l"(a), "l"(b), "l"(c));
    return d;
}
__device__ __forceinline__ float lohi_sum(ull v) {
    unsigned lo, hi;
    asm("mov.b64 {%0, %1}, %2;" : "=r"(lo), "=r"(hi) : "l"(v));
    return __uint_as_float(lo) + __uint_as_float(hi);
}
__device__ __forceinline__ void cp_async16(void* smem_dst, const void* gmem_src) {
    unsigned s = (unsigned)__cvta_generic_to_shared(smem_dst);
    asm volatile("cp.async.cg.shared.global [%0], [%1], 16;" :: "r"(s), "l"(gmem_src));
}

// Chip-wide barrier: monotonic ticket counter (replay-safe, never reset).
__device__ __forceinline__ void grid_barrier() {
    __syncthreads();
    if (threadIdx.x == 0) {
        __threadfence();                       // release: publish this CTA's writes
        unsigned v = atomicAdd(&g_bar, 1u);
        unsigned target = (v / NCTA + 1u) * NCTA;
        unsigned cur;
        do {
            cur = atomicAdd(&g_bar, 0u);
        } while (cur < target);
        __threadfence();                       // acquire
    }
    __syncthreads();
}

// Stage one 512-k chunk of h (all 16 batches) into SMEM via cp.async.
// Chunk = 16 batches x 512 floats = 2048 float4 = 8 iters x 256 threads.
__device__ __forceinline__ void load_chunk(float* dstbase, const float* hsrc,
                                           int c, int tid) {
#pragma unroll
    for (int it = 0; it < 8; ++it) {
        int e  = tid + it * NTHREADS;   // 0..2047
        int b  = e >> 7;                // 128 float4 per batch row
        int k4 = e & 127;
        cp_async16(dstbase + b * HPAD + k4 * 4,
                   hsrc + (size_t)b * RR + (size_t)c * CHUNK + k4 * 4);
    }
    asm volatile("cp.async.commit_group;" ::: "memory");
}

// ---------------- kernel 1: masked input projection ----------------
// proj[t][b][r] = sum_f inputs[b][t][f] * Win[r][f], r < HALF only.
__global__ void __launch_bounds__(256, 2)
proj_kernel(const float* __restrict__ inputs, const float* __restrict__ Win) {
    extern __shared__ float smem[];
    float* sWin = smem;                 // [128][PPAD]
    float* sInp = smem + 128 * PPAD;    // [16][PPAD]

    const int tid = threadIdx.x;
    const int j0  = blockIdx.x * 128;   // output column tile (< HALF)
    const int t0  = blockIdx.y * 4;

    // Load 128x128 W tile
    for (int i = tid; i < 128 * 32; i += 256) {
        int jr = i >> 5, f4 = i & 31;
        float4 v = *(const float4*)(Win + (size_t)(j0 + jr) * FF + f4 * 4);
        float* d = sWin + jr * PPAD + f4 * 4;
        d[0] = v.x; d[1] = v.y; d[2] = v.z; d[3] = v.w;
    }

    const int j  = tid & 127;
    const int hb = tid >> 7;            // 0/1 -> batches hb*8..hb*8+7
    const float* wp = sWin + j * PPAD;

    for (int tt = 0; tt < 4; ++tt) {
        int t = t0 + tt;
        __syncthreads();
        for (int i = tid; i < BATCH * 32; i += 256) {
            int b = i >> 5, f4 = i & 31;
            float4 v = *(const float4*)(inputs + ((size_t)b * TT + t) * FF + f4 * 4);
            float* d = sInp + b * PPAD + f4 * 4;
            d[0] = v.x; d[1] = v.y; d[2] = v.z; d[3] = v.w;
        }
        __syncthreads();

        ull acc[8];
#pragma unroll
        for (int n = 0; n < 8; ++n) acc[n] = 0ull;

#pragma unroll 8
        for (int f = 0; f < FF; f += 2) {
            ull wv = *(const ull*)(wp + f);
#pragma unroll
            for (int jj = 0; jj < 8; ++jj) {
                ull hv = *(const ull*)(sInp + (hb * 8 + jj) * PPAD + f);
                acc[jj] = ffma2(hv, wv, acc[jj]);
            }
        }
#pragma unroll
        for (int jj = 0; jj < 8; ++jj) {
            int b = hb * 8 + jj;
            g_proj[((size_t)t * BATCH + b) * HALF + j0 + j] = lohi_sum(acc[jj]);
        }
    }
}

// ---------------- kernel 2: persistent recurrence ----------------
// CTA c owns rows [c*16, c*16+16) of W_rec (SMEM-stationary).
__global__ void __launch_bounds__(NTHREADS, 1)
esn_kernel(const float* __restrict__ Wrec, const float* __restrict__ bias,
           const float* __restrict__ rstart, float* __restrict__ out) {
    extern __shared__ float smem[];
    float* sW   = smem;                 // [16][WPAD]
    float* sh   = smem + SW_FLOATS;     // 2 x [16][HPAD]
    float* sRed = sh;                   // alias (safe: used after compute done)

    const int tid = threadIdx.x;
    const int cta = blockIdx.x;
    const int w   = tid >> 5;
    const int l   = tid & 31;
    const int bg  = l & 3;              // batch group: batches bg, bg+4, bg+8, bg+12
    const int rg  = l >> 2;             // row group:   rows 2rg, 2rg+1

    // Load this CTA's 16 W rows into padded SMEM (once)
    {
        const float* wsrc = Wrec + (size_t)cta * ROWS_PER_CTA * RR;
        for (int i = tid; i < ROWS_PER_CTA * (RR / 4); i += NTHREADS) {
            int r  = i / (RR / 4);
            int k4 = i % (RR / 4);
            float4 v = *(const float4*)(wsrc + (size_t)r * RR + k4 * 4);
            float* d = sW + r * WPAD + k4 * 4;
            d[0] = v.x; d[1] = v.y; d[2] = v.z; d[3] = v.w;
        }
    }

    // Epilogue constants: thread (eb, er) owns one (batch,row) output
    const int eb = tid >> 4;                     // batch 0..15
    const int er = tid & 15;                     // local row
    const int gr = cta * ROWS_PER_CTA + er;      // global row
    const float bia = bias[gr];

    // Initialize h0 = broadcast(reservoir_start)
    g_h[0][eb * RR + gr] = rstart[gr];
    grid_barrier();

    const float* wrow0 = sW + (2 * rg) * WPAD;
    const float* wrow1 = sW + (2 * rg + 1) * WPAD;

    for (int t = 0; t < TT; ++t) {
        const float* hc = g_h[t & 1];
        float*       hn = g_h[(t + 1) & 1];

        load_chunk(sh, hc, 0, tid);   // prefetch chunk 0 -> buf 0

        ull acc[8];
#pragma unroll
        for (int n = 0; n < 8; ++n) acc[n] = 0ull;

#pragma unroll
        for (int c = 0; c < NCHUNK; ++c) {
            if (c + 1 < NCHUNK) {
                load_chunk(sh + ((c + 1) & 1) * (BATCH * HPAD), hc, c + 1, tid);
                asm volatile("cp.async.wait_group 1;" ::: "memory");
            } else {
                asm volatile("cp.async.wait_group 0;" ::: "memory");
            }
            __syncthreads();          // chunk c resident for all warps

            const float* shb = sh + (c & 1) * (BATCH * HPAD);
            const int kbase = c * CHUNK;
            const float* h0 = shb + (bg)      * HPAD + w * 64;
            const float* h1 = shb + (bg + 4)  * HPAD + w * 64;
            const float* h2 = shb + (bg + 8)  * HPAD + w * 64;
            const float* h3 = shb + (bg + 12) * HPAD + w * 64;
            const float* w0 = wrow0 + kbase + w * 64;
            const float* w1 = wrow1 + kbase + w * 64;

#pragma unroll 8
            for (int kk = 0; kk < 64; kk += 2) {
                ull hv0 = *(const ull*)(h0 + kk);
                ull hv1 = *(const ull*)(h1 + kk);
                ull hv2 = *(const ull*)(h2 + kk);
                ull hv3 = *(const ull*)(h3 + kk);
                ull wv0 = *(const ull*)(w0 + kk);
                ull wv1 = *(const ull*)(w1 + kk);
                acc[0] = ffma2(hv0, wv0, acc[0]);
                acc[1] = ffma2(hv0, wv1, acc[1]);
                acc[2] = ffma2(hv1, wv0, acc[2]);
                acc[3] = ffma2(hv1, wv1, acc[3]);
                acc[4] = ffma2(hv2, wv0, acc[4]);
                acc[5] = ffma2(hv2, wv1, acc[5]);
                acc[6] = ffma2(hv3, wv0, acc[6]);
                acc[7] = ffma2(hv3, wv1, acc[7]);
            }
            __syncthreads();          // chunk c fully consumed before buf reuse
        }

        // Cross-warp reduction of the 16x16 tile (8 K-split partials)
#pragma unroll
        for (int j = 0; j < 4; ++j)
#pragma unroll
            for (int i = 0; i < 2; ++i) {
                int bb = bg + 4 * j, rr = 2 * rg + i;
                sRed[w * 264 + bb * 16 + rr] = lohi_sum(acc[j * 2 + i]);
            }
        __syncthreads();

        float z = 0.f;
#pragma unroll
        for (int ww = 0; ww < 8; ++ww) z += sRed[ww * 264 + tid];
        z += bia;
        if (gr < HALF) z += g_proj[((size_t)t * BATCH + eb) * HALF + gr];

        float hold = hc[eb * RR + gr];
        float hnew = (1.0f - GAMMA) * hold + GAMMA * tanhf(z);
        hn[eb * RR + gr] = hnew;
        if (gr >= HALF)
            out[((size_t)eb * TT + t) * HALF + (gr - HALF)] = hnew;

        grid_barrier();               // publish hn chip-wide before next step
    }
}

// ---------------- launch ----------------
extern "C" void kernel_launch(void* const* d_in, const int* in_sizes, int n_in,
                              void* d_out, int out_size) {
    const float* inputs = (const float*)d_in[0];   // [16,1024,128]
    const float* Win    = (const float*)d_in[1];   // [2048,128]
    const float* Wrec   = (const float*)d_in[2];   // [2048,2048]
    const float* bias   = (const float*)d_in[3];   // [2048]
    const float* rstart = (const float*)d_in[4];   // [2048]
    float* out = (float*)d_out;                    // [16,1024,1024]

    cudaFuncSetAttribute(proj_kernel, cudaFuncAttributeMaxDynamicSharedMemorySize,
                         SMEM_PROJ);
    cudaFuncSetAttribute(esn_kernel, cudaFuncAttributeMaxDynamicSharedMemorySize,
                         SMEM_MAIN);

    dim3 pgrid(HALF / 128, TT / 4, 1);   // 8 x 256 blocks
    proj_kernel<<<pgrid, 256, SMEM_PROJ>>>(inputs, Win);

    esn_kernel<<<NCTA, NTHREADS, SMEM_MAIN>>>(Wrec, bias, rstart, out);
}

// round 14
// speedup vs baseline: 1.3480x; 1.3480x over previous
#include <cuda_runtime.h>
#include <cstdint>

#define BATCH 16
#define TT    1024
#define FF    128
#define RR    2048
#define HALF  1024
#define GAMMA 0.95f

#define NCTA          128
#define ROWS_PER_CTA  16
#define NTHREADS      256
#define CHUNK         512
#define NCHUNK        4

// ---- SMEM layout (floats) ----
// W rows: stride 2050 (even, ==2 mod 8 -> rg*4 rows spread 8 banks apart)
#define WPAD   2050
#define SW_FLOATS   (ROWS_PER_CTA * WPAD)              // 32800
// h chunk rows: base(b) = b*520 + (b>>3)*8  (mid-pad => bgp bank delta 8)
#define HROWF(b)    ((b) * 520 + ((b) >> 3) * 8)
#define HBUF_FLOATS 8336                               // > HROWF(15)+520
#define SH_FLOATS   (2 * HBUF_FLOATS)                  // 16672
#define SMEM_MAIN   ((SW_FLOATS + SH_FLOATS) * 4)      // 197888 B

#define PPAD   130
#define SMEM_PROJ   ((128 * PPAD + BATCH * PPAD) * 4)  // 74880 B

typedef unsigned long long ull;

// ---------------- device globals ----------------
__device__ float    g_proj[(size_t)TT * BATCH * HALF]; // [t][b][r<HALF]
__device__ float    g_h[2][BATCH * RR];                // ping-pong state
__device__ unsigned g_arrive = 0;                      // monotonic arrive counter
__device__ unsigned g_flag   = 0;                      // monotonic round flag

// ---------------- helpers ----------------
__device__ __forceinline__ ull ffma2(ull a, ull b, ull c) {
    ull d;
    asm("fma.rn.f32x2 %0, %1, %2, %3;" : "=l"(d) : "l"(a), "l"(b), "l"(c));
    return d;
}
__device__ __forceinline__ float lohi_sum(ull v) {
    unsigned lo, hi;
    asm("mov.b64 {%0, %1}, %2;" : "=r"(lo), "=r"(hi) : "l"(v));
    return __uint_as_float(lo) + __uint_as_float(hi);
}
__device__ __forceinline__ void cp_async16(void* smem_dst, const void* gmem_src) {
    unsigned s = (unsigned)__cvta_generic_to_shared(smem_dst);
    asm volatile("cp.async.cg.shared.global [%0], [%1], 16;" :: "r"(s), "l"(gmem_src));
}

// Chip-wide barrier. Primitives identical to the proven R12 barrier
// (fence + atomicAdd arrive, atomicAdd(p,0) poll), but arrivals and polls
// use DIFFERENT addresses so pollers never serialize the arrive path.
// Both counters are monotonic -> graph-replay-safe.
__device__ __forceinline__ void grid_barrier() {
    __syncthreads();
    if (threadIdx.x == 0) {
        __threadfence();                                  // release my CTA's writes
        unsigned v = atomicAdd(&g_arrive, 1u);
        unsigned round = v >> 7;                          // global round index
        if ((v & 127u) == 127u) {                         // last arriver
            __threadfence();
            atomicExch(&g_flag, round + 1u);              // broadcast release
        } else {
            while (atomicAdd(&g_flag, 0u) < round + 1u) {}
        }
        __threadfence();                                  // acquire
    }
    __syncthreads();
}

// Stage one 512-k chunk of h (16 batches x 512 floats = 2048 float4).
__device__ __forceinline__ void load_chunk(float* dstbase, const float* hsrc,
                                           int c, int tid) {
#pragma unroll
    for (int it = 0; it < 8; ++it) {
        int e  = tid + it * NTHREADS;   // 0..2047
        int b  = e >> 7;                // 128 float4 per batch row
        int k4 = e & 127;
        cp_async16(dstbase + HROWF(b) + k4 * 4,
                   hsrc + (size_t)b * RR + (size_t)c * CHUNK + k4 * 4);
    }
    asm volatile("cp.async.commit_group;" ::: "memory");
}

// ---------------- kernel 1: masked input projection (unchanged, proven) ----
__global__ void __launch_bounds__(256, 2)
proj_kernel(const float* __restrict__ inputs, const float* __restrict__ Win) {
    extern __shared__ float smem[];
    float* sWin = smem;                 // [128][PPAD]
    float* sInp = smem + 128 * PPAD;    // [16][PPAD]

    const int tid = threadIdx.x;
    const int j0  = blockIdx.x * 128;
    const int t0  = blockIdx.y * 4;

    for (int i = tid; i < 128 * 32; i += 256) {
        int jr = i >> 5, f4 = i & 31;
        float4 v = *(const float4*)(Win + (size_t)(j0 + jr) * FF + f4 * 4);
        float* d = sWin + jr * PPAD + f4 * 4;
        d[0] = v.x; d[1] = v.y; d[2] = v.z; d[3] = v.w;
    }

    const int j  = tid & 127;
    const int hb = tid >> 7;
    const float* wp = sWin + j * PPAD;

    for (int tt = 0; tt < 4; ++tt) {
        int t = t0 + tt;
        __syncthreads();
        for (int i = tid; i < BATCH * 32; i += 256) {
            int b = i >> 5, f4 = i & 31;
            float4 v = *(const float4*)(inputs + ((size_t)b * TT + t) * FF + f4 * 4);
            float* d = sInp + b * PPAD + f4 * 4;
            d[0] = v.x; d[1] = v.y; d[2] = v.z; d[3] = v.w;
        }
        __syncthreads();

        ull acc[8];
#pragma unroll
        for (int n = 0; n < 8; ++n) acc[n] = 0ull;

#pragma unroll 8
        for (int f = 0; f < FF; f += 2) {
            ull wv = *(const ull*)(wp + f);
#pragma unroll
            for (int jj = 0; jj < 8; ++jj) {
                ull hv = *(const ull*)(sInp + (hb * 8 + jj) * PPAD + f);
                acc[jj] = ffma2(hv, wv, acc[jj]);
            }
        }
#pragma unroll
        for (int jj = 0; jj < 8; ++jj) {
            int b = hb * 8 + jj;
            g_proj[((size_t)t * BATCH + b) * HALF + j0 + j] = lohi_sum(acc[jj]);
        }
    }
}

// ---------------- kernel 2: persistent recurrence ----------------
// CTA c owns rows [c*16, c*16+16). Register tile per thread: 4 rows x 8 batches.
// Thread decomposition: pos = tid&7 (rg = pos&3, bgp = pos>>2), ks = tid>>3.
// K covered per thread: k = chunk*512 + it*64 + ks*2, it = 0..7 (ull per step).
__global__ void __launch_bounds__(NTHREADS, 1)
esn_kernel(const float* __restrict__ Wrec, const float* __restrict__ bias,
           const float* __restrict__ rstart, float* __restrict__ out) {
    extern __shared__ float smem[];
    float* sW   = smem;                 // [16][WPAD]
    float* sh   = smem + SW_FLOATS;     // 2 x HBUF_FLOATS
    float* sRed = sh;                   // alias: 256*33 = 8448 <= 16672 floats

    const int tid = threadIdx.x;
    const int cta = blockIdx.x;
    const int rg  = tid & 3;            // row group: rows rg*4 .. rg*4+3
    const int bgp = (tid >> 2) & 1;     // batch group: bgp*8 .. bgp*8+7
    const int ks  = tid >> 3;           // k-split 0..31
    const int ks2 = ks * 2;

    // One-time W fill (ull stores; rows at stride WPAD=2050)
    {
        const float* wsrc = Wrec + (size_t)cta * ROWS_PER_CTA * RR;
        for (int i = tid; i < ROWS_PER_CTA * (RR / 2); i += NTHREADS) {
            int r  = i >> 10;           // RR/2 = 1024 ull per row
            int ku = i & 1023;
            *(ull*)(sW + r * WPAD + ku * 2) =
                *(const ull*)(wsrc + (size_t)r * RR + ku * 2);
        }
    }

    // Epilogue mapping: thread owns output o = tid = 64*rg + 16*i' ...
    // decoded as: local row = tid>>4, batch = tid&15.
    const int er = tid >> 4;                     // local row 0..15
    const int eb = tid & 15;                     // batch 0..15
    const int gr = cta * ROWS_PER_CTA + er;
    const float bia = bias[gr];

    // h0 = broadcast(reservoir_start)
    g_h[0][eb * RR + gr] = rstart[gr];
    grid_barrier();

    const float* wbase = sW + (rg * 4) * WPAD;   // + i*WPAD
    const int hbase_off = bgp * (8 * 520 + 8);   // + j*520

    for (int t = 0; t < TT; ++t) {
        const float* hc = g_h[t & 1];
        float*       hn = g_h[(t + 1) & 1];

        load_chunk(sh, hc, 0, tid);              // prefetch chunk 0 -> buf 0

        // Early epilogue operand loads (plain LDG, R12-proven; values fixed
        // for the whole step, latency hidden under the GEMM).
        const float hold  = hc[eb * RR + gr];
        const float projv = (gr < HALF)
                          ? g_proj[((size_t)t * BATCH + eb) * HALF + gr]
                          : 0.0f;

        ull acc[32];
#pragma unroll
        for (int n = 0; n < 32; ++n) acc[n] = 0ull;

#pragma unroll
        for (int c = 0; c < NCHUNK; ++c) {
            if (c + 1 < NCHUNK) {
                load_chunk(sh + ((c + 1) & 1) * HBUF_FLOATS, hc, c + 1, tid);
                asm volatile("cp.async.wait_group 1;" ::: "memory");
            } else {
                asm volatile("cp.async.wait_group 0;" ::: "memory");
            }
            __syncthreads();

            const float* hb = sh + (c & 1) * HBUF_FLOATS + hbase_off;
            const float* wb = wbase + c * CHUNK;

#pragma unroll
            for (int it = 0; it < 8; ++it) {
                const int kl = it * 64 + ks2;
                ull hv[8], wv[4];
#pragma unroll
                for (int j = 0; j < 8; ++j)
                    hv[j] = *(const ull*)(hb + j * 520 + kl);
#pragma unroll
                for (int i = 0; i < 4; ++i)
                    wv[i] = *(const ull*)(wb + i * WPAD + kl);
#pragma unroll
                for (int i = 0; i < 4; ++i)
#pragma unroll
                    for (int j = 0; j < 8; ++j)
                        acc[i * 8 + j] = ffma2(hv[j], wv[i], acc[i * 8 + j]);
            }
            __syncthreads();
        }

        // K-split reduction: output o = (rg*4+i)*16 + bgp*8 + j, 32 partials.
        // Write slot swizzled: col = (ks + 4*rg) & 31, stride 33.
#pragma unroll
        for (int i = 0; i < 4; ++i)
#pragma unroll
            for (int j = 0; j < 8; ++j) {
                int o = (rg * 4 + i) * 16 + bgp * 8 + j;
                int col = (ks + 4 * rg) & 31;
                sRed[o * 33 + col] = lohi_sum(acc[i * 8 + j]);
            }
        __syncthreads();

        // Thread tid sums output o = tid (rg_o = o>>6 fixes the swizzle).
        float z = 0.f;
        {
            const int rgo4 = (tid >> 6) * 4;
            const float* rp = sRed + tid * 33;
#pragma unroll
            for (int s = 0; s < 32; ++s) z += rp[(s + rgo4) & 31];
        }
        z += bia + projv;

        float hnew = (1.0f - GAMMA) * hold + GAMMA * tanhf(z);
        hn[eb * RR + gr] = hnew;
        if (gr >= HALF)
            out[((size_t)eb * TT + t) * HALF + (gr - HALF)] = hnew;

        grid_barrier();               // publish hn chip-wide before next step
    }
}

// ---------------- launch ----------------
extern "C" void kernel_launch(void* const* d_in, const int* in_sizes, int n_in,
                              void* d_out, int out_size) {
    const float* inputs = (const float*)d_in[0];   // [16,1024,128]
    const float* Win    = (const float*)d_in[1];   // [2048,128]
    const float* Wrec   = (const float*)d_in[2];   // [2048,2048]
    const float* bias   = (const float*)d_in[3];   // [2048]
    const float* rstart = (const float*)d_in[4];   // [2048]
    float* out = (float*)d_out;                    // [16,1024,1024]

    cudaFuncSetAttribute(proj_kernel, cudaFuncAttributeMaxDynamicSharedMemorySize,
                         SMEM_PROJ);
    cudaFuncSetAttribute(esn_kernel, cudaFuncAttributeMaxDynamicSharedMemorySize,
                         SMEM_MAIN);

    dim3 pgrid(HALF / 128, TT / 4, 1);   // 8 x 256 blocks
    proj_kernel<<<pgrid, 256, SMEM_PROJ>>>(inputs, Win);

    esn_kernel<<<NCTA, NTHREADS, SMEM_MAIN>>>(Wrec, bias, rstart, out);
}